// round 12
// baseline (speedup 1.0000x reference)
#include <cuda_runtime.h>
#include <math.h>

#define BB 256
#define NN 384
#define DD 128
#define NEGV -1e9f
#define GSTR 132
#define CH 32

// ---------------- device scratch (static, no allocation) ----------------
__device__ float g_A[DD * DD];
__device__ float g_hT[BB * DD * NN];
__device__ float g_MT[BB * DD * NN];
__device__ float g_G[(size_t)BB * NN * NN];
__device__ float g_hbarA[BB * DD];
__device__ float g_vA[DD];
__device__ float g_sHB[BB * NN];
__device__ float g_sV[BB * NN];

// ---------------- packed fp32x2 helpers ----------------
__device__ __forceinline__ void ffma2(unsigned long long& d,
                                      unsigned long long a,
                                      unsigned long long b) {
    asm("fma.rn.f32x2 %0, %1, %2, %0;" : "+l"(d) : "l"(a), "l"(b));
}
__device__ __forceinline__ unsigned long long pack2(float lo, float hi) {
    unsigned long long r;
    asm("mov.b64 %0, {%1, %2};" : "=l"(r) : "f"(lo), "f"(hi));
    return r;
}

// order-preserving float<->u32 (total order == fp32 compare; no NaNs here)
__device__ __forceinline__ unsigned orderf(float f) {
    unsigned b = __float_as_uint(f);
    return (b & 0x80000000u) ? ~b : (b | 0x80000000u);
}
__device__ __forceinline__ float unorderf(unsigned o) {
    unsigned b = (o & 0x80000000u) ? (o & 0x7fffffffu) : ~o;
    return __uint_as_float(b);
}

// ---------------------------------------------------------------------------
// Bit-faithful port of XLA's EmitFastTanh (with_fma=true). DO NOT TOUCH.
// ---------------------------------------------------------------------------
__device__ __forceinline__ float xla_tanh(float x) {
    const float kClamp = 7.99881172180175781f;
    float xc = fminf(fmaxf(x, -kClamp), kClamp);
    float x2 = xc * xc;
    float p = fmaf(x2, -2.76076847742355e-16f, 2.00018790482477e-13f);
    p = fmaf(x2, p, -8.60467152213735e-11f);
    p = fmaf(x2, p,  5.12229709037114e-08f);
    p = fmaf(x2, p,  1.48572235717979e-05f);
    p = fmaf(x2, p,  6.37261928875436e-04f);
    p = fmaf(x2, p,  4.89352455891786e-03f);
    p = xc * p;
    float q = fmaf(x2, 1.19825839466702e-06f, 1.18534705686654e-04f);
    q = fmaf(x2, q, 2.26843463243900e-03f);
    q = fmaf(x2, q, 4.89352518554385e-03f);
    float r = p / q;
    return (fabsf(x) < 0.0004f) ? x : r;
}

// ---------------------------------------------------------------------------
__global__ void kA(const float* __restrict__ qv, const float* __restrict__ kv) {
    __shared__ float wk[DD];
    int m = blockIdx.x, k = threadIdx.x;
    wk[k] = kv[m * DD + k];
    __syncthreads();
    float s = 0.f;
    #pragma unroll 8
    for (int j = 0; j < DD; j++) s = fmaf(qv[k * DD + j], wk[j], s);
    g_A[k * DD + m] = s;
}

__global__ void kT(const float* __restrict__ hvec) {
    __shared__ float tile[32][33];
    int b = blockIdx.z;
    int n0 = blockIdx.x * 32, d0 = blockIdx.y * 32;
    int tx = threadIdx.x, ty = threadIdx.y;
    #pragma unroll
    for (int i = 0; i < 32; i += 8)
        tile[ty + i][tx] = hvec[((size_t)b * NN + n0 + ty + i) * DD + d0 + tx];
    __syncthreads();
    #pragma unroll
    for (int i = 0; i < 32; i += 8)
        g_hT[((size_t)b * DD + d0 + ty + i) * NN + n0 + tx] = tile[tx][ty + i];
}

__global__ void kVec(const float* __restrict__ hbar,
                     const float* __restrict__ vec1,
                     const float* __restrict__ vecf) {
    __shared__ float hb[DD], vv[DD];
    int b = blockIdx.x, m = threadIdx.x;
    hb[m] = hbar[b * DD + m];
    if (b == 0) vv[m] = vec1[m] + vecf[m];
    __syncthreads();
    float acc = 0.f;
    #pragma unroll 8
    for (int k = 0; k < DD; k++) acc = fmaf(hb[k], g_A[k * DD + m], acc);
    g_hbarA[b * DD + m] = acc;
    if (b == 0) {
        float a2 = 0.f;
        #pragma unroll 8
        for (int k = 0; k < DD; k++) a2 = fmaf(vv[k], g_A[k * DD + m], a2);
        g_vA[m] = a2;
    }
}

__global__ void __launch_bounds__(NN) kSB() {
    __shared__ float sb[DD], sv[DD];
    int b = blockIdx.x, n = threadIdx.x;
    if (n < DD) { sb[n] = g_hbarA[b * DD + n]; sv[n] = g_vA[n]; }
    __syncthreads();
    const float* hTb = g_hT + (size_t)b * DD * NN;
    float a0 = 0.f, a1 = 0.f, a2 = 0.f, a3 = 0.f;
    float c0 = 0.f, c1 = 0.f, c2 = 0.f, c3 = 0.f;
    #pragma unroll 8
    for (int d = 0; d < DD; d += 4) {
        float h0 = hTb[(size_t)(d + 0) * NN + n];
        float h1 = hTb[(size_t)(d + 1) * NN + n];
        float h2 = hTb[(size_t)(d + 2) * NN + n];
        float h3 = hTb[(size_t)(d + 3) * NN + n];
        a0 = fmaf(h0, sb[d + 0], a0); c0 = fmaf(h0, sv[d + 0], c0);
        a1 = fmaf(h1, sb[d + 1], a1); c1 = fmaf(h1, sv[d + 1], c1);
        a2 = fmaf(h2, sb[d + 2], a2); c2 = fmaf(h2, sv[d + 2], c2);
        a3 = fmaf(h3, sb[d + 3], a3); c3 = fmaf(h3, sv[d + 3], c3);
    }
    g_sHB[b * NN + n] = (a0 + a1) + (a2 + a3);
    g_sV[b * NN + n]  = (c0 + c1) + (c2 + c3);
}

// ---------------------------------------------------------------------------
// K_Gemm (unchanged): cp.async double-buffered 128x128 tile.
// ---------------------------------------------------------------------------
extern __shared__ float dynsm[];
__device__ __forceinline__ void cpa16(unsigned s, const void* g) {
    asm volatile("cp.async.ca.shared.global [%0], [%1], 16;" :: "r"(s), "l"(g));
}

__global__ void __launch_bounds__(256, 2)
kGemm(float* __restrict__ Cg, const float* __restrict__ Ag,
      const float* __restrict__ Bg,
      size_t sAb, size_t sBb, size_t sCb, int ldA, int ldB, int ldC) {
    int b = blockIdx.z;
    int r0 = blockIdx.y * 128, c0 = blockIdx.x * 128;
    int tid = threadIdx.x;
    int ty = tid >> 4, tx = tid & 15;

    const float* Ab = Ag + (size_t)b * sAb;
    const float* Bb = Bg + (size_t)b * sBb;
    unsigned sbase = (unsigned)__cvta_generic_to_shared(dynsm);

    unsigned long long acc2[32];
    #pragma unroll
    for (int j = 0; j < 32; j++) acc2[j] = 0ull;

    auto issue = [&](int c, int st) {
        unsigned Ms = sbase + (unsigned)(st * 2 * CH * GSTR) * 4u;
        unsigned Hs = Ms + (unsigned)(CH * GSTR) * 4u;
        const float* Asrc = Ab + (size_t)(c * CH) * ldA + r0;
        const float* Bsrc = Bb + (size_t)(c * CH) * ldB + c0;
        #pragma unroll
        for (int i = tid; i < CH * 32; i += 256) {
            int d = i >> 5, v = i & 31;
            cpa16(Ms + (unsigned)(d * GSTR + v * 4) * 4u, Asrc + (size_t)d * ldA + v * 4);
            cpa16(Hs + (unsigned)(d * GSTR + v * 4) * 4u, Bsrc + (size_t)d * ldB + v * 4);
        }
        asm volatile("cp.async.commit_group;");
    };

    issue(0, 0);
    #pragma unroll
    for (int c = 0; c < 4; c++) {
        if (c < 3) {
            issue(c + 1, (c + 1) & 1);
            asm volatile("cp.async.wait_group 1;");
        } else {
            asm volatile("cp.async.wait_group 0;");
        }
        __syncthreads();
        float* Ms = dynsm + (c & 1) * 2 * CH * GSTR;
        float* Hs = Ms + CH * GSTR;
        #pragma unroll 4
        for (int d = 0; d < CH; d++) {
            const float4* ar = (const float4*)(Ms + d * GSTR + ty * 8);
            float4 A0 = ar[0], A1 = ar[1];
            ulonglong2 B0 = *(const ulonglong2*)(Hs + d * GSTR + tx * 4);
            ulonglong2 B1 = *(const ulonglong2*)(Hs + d * GSTR + 64 + tx * 4);
            unsigned long long bl[4] = {B0.x, B0.y, B1.x, B1.y};
            float af[8] = {A0.x, A0.y, A0.z, A0.w, A1.x, A1.y, A1.z, A1.w};
            #pragma unroll
            for (int r = 0; r < 8; r++) {
                unsigned long long ad = pack2(af[r], af[r]);
                #pragma unroll
                for (int cc = 0; cc < 4; cc++) ffma2(acc2[r * 4 + cc], bl[cc], ad);
            }
        }
        __syncthreads();
    }
    #pragma unroll
    for (int r = 0; r < 8; r++) {
        float* crow = Cg + (size_t)b * sCb + (size_t)(r0 + ty * 8 + r) * ldC + c0;
        ulonglong2 w0; w0.x = acc2[r * 4 + 0]; w0.y = acc2[r * 4 + 1];
        ulonglong2 w1; w1.x = acc2[r * 4 + 2]; w1.y = acc2[r * 4 + 3];
        *(ulonglong2*)(crow + tx * 4) = w0;
        *(ulonglong2*)(crow + 64 + tx * 4) = w1;
    }
}

// ---------------------------------------------------------------------------
// K_D: one warp per batch, zero barriers, SATURATION FAST PATH + pipelining.
// Clamped tanh inputs (|x| >= CL) all map to one constant -> skip rational/div
// and expf for ~97% of nodes; bit-identical to the slow path by construction.
// Loop order: scores -> argmax redux -> issue next G-row loads -> es/logp.
// ---------------------------------------------------------------------------
__global__ void __launch_bounds__(32) kD(float* __restrict__ out) {
    const int b = blockIdx.x, lane = threadIdx.x;
    const float CL = 7.99881172180175781f;
    const float SATP  = 10.f * xla_tanh(40.f);   // == reference clamped value
    const float SATN  = 10.f * xla_tanh(-40.f);  // exact negation (P odd, Q even)
    const float ESATP = __expf(SATP);
    const float ESATN = __expf(SATN);

    float sHB[12], sV[12], sbf[12], gv[12];
    #pragma unroll
    for (int j = 0; j < 12; j++) {
        sHB[j] = g_sHB[b * NN + j * 32 + lane];
        sV[j]  = g_sV [b * NN + j * 32 + lane];
    }

    const float* Gb = g_G + (size_t)b * NN * NN;
    unsigned vismask = 0;
    float logp = 0.f;
    int a = 0;

    for (int t = 0; t < NN; t++) {
        float best = -3.0e38f;
        int   nbest = 0x7fffffff;
        float ev[12];
        #pragma unroll
        for (int j = 0; j < 12; j++) {
            float s;
            if (t == 0)      s = sHB[j] + sV[j];
            else {
                if (t == 1)  sbf[j] = sHB[j] + gv[j];
                s = sbf[j] + gv[j];
            }
            float x = s * 0.25f;
            bool visited = (vismask >> j) & 1u;
            float score, e;
            if (x >= CL)       { score = SATP; e = ESATP; }
            else if (x <= -CL) { score = SATN; e = ESATN; }
            else {               score = 10.f * xla_tanh(x); e = __expf(score); }
            float masked = visited ? NEGV : score;
            ev[j] = visited ? 0.f : e;
            if (masked > best) { best = masked; nbest = j * 32 + lane; }
        }

        // warp argmax, lowest-index tie-break (HW redux)
        unsigned ov   = orderf(best);
        unsigned wmax = __reduce_max_sync(0xffffffffu, ov);
        unsigned cand = (ov == wmax) ? (unsigned)nbest : 0xffffffffu;
        a = (int)__reduce_min_sync(0xffffffffu, cand);
        if ((a & 31) == lane) vismask |= 1u << (a >> 5);

        // issue next G-row loads NOW (overlap with es/logp below)
        {
            const float* grow = Gb + (size_t)a * NN + lane;
            #pragma unroll
            for (int j = 0; j < 12; j++) gv[j] = __ldg(grow + j * 32);
        }

        // exp-sum (fixed j-ascending order per lane, then butterfly)
        float es = 0.f;
        #pragma unroll
        for (int j = 0; j < 12; j++) es += ev[j];
        #pragma unroll
        for (int o = 16; o > 0; o >>= 1)
            es += __shfl_xor_sync(0xffffffffu, es, o);

        if (lane == 0) {
            out[t * BB + b] = (float)a;
            logp += unorderf(wmax) - __logf(es);
        }
    }
    if (lane == 0) out[NN * BB + b] = logp;
}

// ---------------------------------------------------------------------------
extern "C" void kernel_launch(void* const* d_in, const int* in_sizes, int n_in,
                              void* d_out, int out_size) {
    const float* hvec = (const float*)d_in[0];
    const float* hbar = (const float*)d_in[1];
    const float* qvp  = (const float*)d_in[2];
    const float* kvp  = (const float*)d_in[3];
    const float* vec1 = (const float*)d_in[4];
    const float* vecf = (const float*)d_in[5];
    float* out = (float*)d_out;

    const int smG = 4 * CH * GSTR * 4;   // 67584 B
    cudaFuncSetAttribute(kGemm, cudaFuncAttributeMaxDynamicSharedMemorySize, smG);

    float *pA, *pHT, *pMT, *pG;
    cudaGetSymbolAddress((void**)&pA,  g_A);
    cudaGetSymbolAddress((void**)&pHT, g_hT);
    cudaGetSymbolAddress((void**)&pMT, g_MT);
    cudaGetSymbolAddress((void**)&pG,  g_G);

    kA<<<DD, DD>>>(qvp, kvp);
    kT<<<dim3(NN / 32, DD / 32, BB), dim3(32, 8)>>>(hvec);
    kVec<<<BB, DD>>>(hbar, vec1, vecf);
    kSB<<<BB, NN>>>();
    kGemm<<<dim3(NN / 128, 1, BB), 256, smG>>>(
        pMT, pA, pHT, 0, (size_t)DD * NN, (size_t)DD * NN, DD, NN, NN);
    kGemm<<<dim3(NN / 128, NN / 128, BB), 256, smG>>>(
        pG, pMT, pHT, (size_t)DD * NN, (size_t)DD * NN, (size_t)NN * NN, NN, NN, NN);
    kD<<<BB, 32>>>(out);
}

// round 13
// speedup vs baseline: 1.1770x; 1.1770x over previous
#include <cuda_runtime.h>
#include <math.h>

#define BB 256
#define NN 384
#define DD 128
#define NEGV -1e9f
#define GSTR 132
#define CH 32

// ---------------- device scratch (static, no allocation) ----------------
__device__ float g_A[DD * DD];
__device__ float g_hT[BB * DD * NN];
__device__ float g_MT[BB * DD * NN];
__device__ float g_G[(size_t)BB * NN * NN];
__device__ float g_hbarA[BB * DD];
__device__ float g_vA[DD];
__device__ float g_sHB[BB * NN];
__device__ float g_sV[BB * NN];

// ---------------- packed fp32x2 helpers ----------------
__device__ __forceinline__ void ffma2(unsigned long long& d,
                                      unsigned long long a,
                                      unsigned long long b) {
    asm("fma.rn.f32x2 %0, %1, %2, %0;" : "+l"(d) : "l"(a), "l"(b));
}
__device__ __forceinline__ unsigned long long pack2(float lo, float hi) {
    unsigned long long r;
    asm("mov.b64 %0, {%1, %2};" : "=l"(r) : "f"(lo), "f"(hi));
    return r;
}

// order-preserving float<->u32 (total order == fp32 compare; no NaNs here)
__device__ __forceinline__ unsigned orderf(float f) {
    unsigned b = __float_as_uint(f);
    return (b & 0x80000000u) ? ~b : (b | 0x80000000u);
}
__device__ __forceinline__ float unorderf(unsigned o) {
    unsigned b = (o & 0x80000000u) ? (o & 0x7fffffffu) : ~o;
    return __uint_as_float(b);
}

// ---------------------------------------------------------------------------
// Bit-faithful port of XLA's EmitFastTanh (with_fma=true). DO NOT TOUCH.
// ---------------------------------------------------------------------------
__device__ __forceinline__ float xla_tanh(float x) {
    const float kClamp = 7.99881172180175781f;
    float xc = fminf(fmaxf(x, -kClamp), kClamp);
    float x2 = xc * xc;
    float p = fmaf(x2, -2.76076847742355e-16f, 2.00018790482477e-13f);
    p = fmaf(x2, p, -8.60467152213735e-11f);
    p = fmaf(x2, p,  5.12229709037114e-08f);
    p = fmaf(x2, p,  1.48572235717979e-05f);
    p = fmaf(x2, p,  6.37261928875436e-04f);
    p = fmaf(x2, p,  4.89352455891786e-03f);
    p = xc * p;
    float q = fmaf(x2, 1.19825839466702e-06f, 1.18534705686654e-04f);
    q = fmaf(x2, q, 2.26843463243900e-03f);
    q = fmaf(x2, q, 4.89352518554385e-03f);
    float r = p / q;
    return (fabsf(x) < 0.0004f) ? x : r;
}

// ---------------------------------------------------------------------------
__global__ void kA(const float* __restrict__ qv, const float* __restrict__ kv) {
    __shared__ float wk[DD];
    int m = blockIdx.x, k = threadIdx.x;
    wk[k] = kv[m * DD + k];
    __syncthreads();
    float s = 0.f;
    #pragma unroll 8
    for (int j = 0; j < DD; j++) s = fmaf(qv[k * DD + j], wk[j], s);
    g_A[k * DD + m] = s;
}

__global__ void kT(const float* __restrict__ hvec) {
    __shared__ float tile[32][33];
    int b = blockIdx.z;
    int n0 = blockIdx.x * 32, d0 = blockIdx.y * 32;
    int tx = threadIdx.x, ty = threadIdx.y;
    #pragma unroll
    for (int i = 0; i < 32; i += 8)
        tile[ty + i][tx] = hvec[((size_t)b * NN + n0 + ty + i) * DD + d0 + tx];
    __syncthreads();
    #pragma unroll
    for (int i = 0; i < 32; i += 8)
        g_hT[((size_t)b * DD + d0 + ty + i) * NN + n0 + tx] = tile[tx][ty + i];
}

__global__ void kVec(const float* __restrict__ hbar,
                     const float* __restrict__ vec1,
                     const float* __restrict__ vecf) {
    __shared__ float hb[DD], vv[DD];
    int b = blockIdx.x, m = threadIdx.x;
    hb[m] = hbar[b * DD + m];
    if (b == 0) vv[m] = vec1[m] + vecf[m];
    __syncthreads();
    float acc = 0.f;
    #pragma unroll 8
    for (int k = 0; k < DD; k++) acc = fmaf(hb[k], g_A[k * DD + m], acc);
    g_hbarA[b * DD + m] = acc;
    if (b == 0) {
        float a2 = 0.f;
        #pragma unroll 8
        for (int k = 0; k < DD; k++) a2 = fmaf(vv[k], g_A[k * DD + m], a2);
        g_vA[m] = a2;
    }
}

__global__ void __launch_bounds__(NN) kSB() {
    __shared__ float sb[DD], sv[DD];
    int b = blockIdx.x, n = threadIdx.x;
    if (n < DD) { sb[n] = g_hbarA[b * DD + n]; sv[n] = g_vA[n]; }
    __syncthreads();
    const float* hTb = g_hT + (size_t)b * DD * NN;
    float a0 = 0.f, a1 = 0.f, a2 = 0.f, a3 = 0.f;
    float c0 = 0.f, c1 = 0.f, c2 = 0.f, c3 = 0.f;
    #pragma unroll 8
    for (int d = 0; d < DD; d += 4) {
        float h0 = hTb[(size_t)(d + 0) * NN + n];
        float h1 = hTb[(size_t)(d + 1) * NN + n];
        float h2 = hTb[(size_t)(d + 2) * NN + n];
        float h3 = hTb[(size_t)(d + 3) * NN + n];
        a0 = fmaf(h0, sb[d + 0], a0); c0 = fmaf(h0, sv[d + 0], c0);
        a1 = fmaf(h1, sb[d + 1], a1); c1 = fmaf(h1, sv[d + 1], c1);
        a2 = fmaf(h2, sb[d + 2], a2); c2 = fmaf(h2, sv[d + 2], c2);
        a3 = fmaf(h3, sb[d + 3], a3); c3 = fmaf(h3, sv[d + 3], c3);
    }
    g_sHB[b * NN + n] = (a0 + a1) + (a2 + a3);
    g_sV[b * NN + n]  = (c0 + c1) + (c2 + c3);
}

// ---------------------------------------------------------------------------
// K_Gemm (unchanged): cp.async double-buffered 128x128 tile.
// ---------------------------------------------------------------------------
extern __shared__ float dynsm[];
__device__ __forceinline__ void cpa16(unsigned s, const void* g) {
    asm volatile("cp.async.ca.shared.global [%0], [%1], 16;" :: "r"(s), "l"(g));
}

__global__ void __launch_bounds__(256, 2)
kGemm(float* __restrict__ Cg, const float* __restrict__ Ag,
      const float* __restrict__ Bg,
      size_t sAb, size_t sBb, size_t sCb, int ldA, int ldB, int ldC) {
    int b = blockIdx.z;
    int r0 = blockIdx.y * 128, c0 = blockIdx.x * 128;
    int tid = threadIdx.x;
    int ty = tid >> 4, tx = tid & 15;

    const float* Ab = Ag + (size_t)b * sAb;
    const float* Bb = Bg + (size_t)b * sBb;
    unsigned sbase = (unsigned)__cvta_generic_to_shared(dynsm);

    unsigned long long acc2[32];
    #pragma unroll
    for (int j = 0; j < 32; j++) acc2[j] = 0ull;

    auto issue = [&](int c, int st) {
        unsigned Ms = sbase + (unsigned)(st * 2 * CH * GSTR) * 4u;
        unsigned Hs = Ms + (unsigned)(CH * GSTR) * 4u;
        const float* Asrc = Ab + (size_t)(c * CH) * ldA + r0;
        const float* Bsrc = Bb + (size_t)(c * CH) * ldB + c0;
        #pragma unroll
        for (int i = tid; i < CH * 32; i += 256) {
            int d = i >> 5, v = i & 31;
            cpa16(Ms + (unsigned)(d * GSTR + v * 4) * 4u, Asrc + (size_t)d * ldA + v * 4);
            cpa16(Hs + (unsigned)(d * GSTR + v * 4) * 4u, Bsrc + (size_t)d * ldB + v * 4);
        }
        asm volatile("cp.async.commit_group;");
    };

    issue(0, 0);
    #pragma unroll
    for (int c = 0; c < 4; c++) {
        if (c < 3) {
            issue(c + 1, (c + 1) & 1);
            asm volatile("cp.async.wait_group 1;");
        } else {
            asm volatile("cp.async.wait_group 0;");
        }
        __syncthreads();
        float* Ms = dynsm + (c & 1) * 2 * CH * GSTR;
        float* Hs = Ms + CH * GSTR;
        #pragma unroll 4
        for (int d = 0; d < CH; d++) {
            const float4* ar = (const float4*)(Ms + d * GSTR + ty * 8);
            float4 A0 = ar[0], A1 = ar[1];
            ulonglong2 B0 = *(const ulonglong2*)(Hs + d * GSTR + tx * 4);
            ulonglong2 B1 = *(const ulonglong2*)(Hs + d * GSTR + 64 + tx * 4);
            unsigned long long bl[4] = {B0.x, B0.y, B1.x, B1.y};
            float af[8] = {A0.x, A0.y, A0.z, A0.w, A1.x, A1.y, A1.z, A1.w};
            #pragma unroll
            for (int r = 0; r < 8; r++) {
                unsigned long long ad = pack2(af[r], af[r]);
                #pragma unroll
                for (int cc = 0; cc < 4; cc++) ffma2(acc2[r * 4 + cc], bl[cc], ad);
            }
        }
        __syncthreads();
    }
    #pragma unroll
    for (int r = 0; r < 8; r++) {
        float* crow = Cg + (size_t)b * sCb + (size_t)(r0 + ty * 8 + r) * ldC + c0;
        ulonglong2 w0; w0.x = acc2[r * 4 + 0]; w0.y = acc2[r * 4 + 1];
        ulonglong2 w1; w1.x = acc2[r * 4 + 2]; w1.y = acc2[r * 4 + 3];
        *(ulonglong2*)(crow + tx * 4) = w0;
        *(ulonglong2*)(crow + 64 + tx * 4) = w1;
    }
}

// ---------------------------------------------------------------------------
// K_D: one warp per batch. Lane owns nodes n = lane*12 + r (r = 0..11).
// Branchless tanh (R11), next-row loads issued immediately after argmax,
// es/logf bookkeeping off the critical chain, float4 G-row loads,
// phased L2 prefetch of remaining rows in the second half of the route.
// Tie-break exact: per-lane ascending-r strict '>' keeps lowest n in lane;
// redux-min over candidates gives lowest n among value ties.
// ---------------------------------------------------------------------------
__global__ void __launch_bounds__(32) kD(float* __restrict__ out) {
    const int b = blockIdx.x, lane = threadIdx.x;
    const int nb = lane * 12;

    float sHB[12], sV[12], sbf[12], gv[12];
    {
        const float4* p1 = (const float4*)(g_sHB + b * NN + nb);
        const float4* p2 = (const float4*)(g_sV  + b * NN + nb);
        #pragma unroll
        for (int q = 0; q < 3; q++) {
            float4 v1 = __ldg(p1 + q), v2 = __ldg(p2 + q);
            sHB[4*q+0] = v1.x; sHB[4*q+1] = v1.y; sHB[4*q+2] = v1.z; sHB[4*q+3] = v1.w;
            sV [4*q+0] = v2.x; sV [4*q+1] = v2.y; sV [4*q+2] = v2.z; sV [4*q+3] = v2.w;
        }
    }

    const float* Gb = g_G + (size_t)b * NN * NN;
    unsigned vismask = 0;
    float logp = 0.f;
    int a = 0;

    for (int t = 0; t < NN; t++) {
        float best = -3.0e38f;
        int   nbest = 0x7fffffff;
        float es = 0.f;
        #pragma unroll
        for (int r = 0; r < 12; r++) {
            float s;
            if (t == 0)      s = sHB[r] + sV[r];
            else {
                if (t == 1)  sbf[r] = sHB[r] + gv[r];
                s = sbf[r] + gv[r];
            }
            float score  = 10.f * xla_tanh(s * 0.25f);
            bool visited = (vismask >> r) & 1u;
            float masked = visited ? NEGV : score;
            es += visited ? 0.f : __expf(score);
            if (masked > best) { best = masked; nbest = nb + r; }
        }

        // warp argmax, lowest-index tie-break (HW redux)
        unsigned ov   = orderf(best);
        unsigned wmax = __reduce_max_sync(0xffffffffu, ov);
        unsigned cand = (ov == wmax) ? (unsigned)nbest : 0xffffffffu;
        a = (int)__reduce_min_sync(0xffffffffu, cand);
        if (a >= nb && a < nb + 12) vismask |= 1u << (a - nb);

        // CRITICAL: issue next G-row loads immediately (3x LDG.128 per lane)
        {
            const float4* gp = (const float4*)(Gb + (size_t)a * NN + nb);
            #pragma unroll
            for (int q = 0; q < 3; q++) {
                float4 g4 = __ldg(gp + q);
                gv[4*q+0] = g4.x; gv[4*q+1] = g4.y; gv[4*q+2] = g4.z; gv[4*q+3] = g4.w;
            }
        }

        // phased L2 prefetch of this lane's remaining rows (read-once data;
        // from t>=128 the leftover set (~50 MB across batches) fits L2)
        if (t >= 128 && (t & 63) == 0) {
            #pragma unroll
            for (int r = 0; r < 12; r++) {
                if (!((vismask >> r) & 1u)) {
                    const char* base = (const char*)(Gb + (size_t)(nb + r) * NN);
                    #pragma unroll
                    for (int l = 0; l < 12; l++)
                        asm volatile("prefetch.global.L2 [%0];" :: "l"(base + l * 128));
                }
            }
        }

        // logp bookkeeping, off the critical chain
        #pragma unroll
        for (int o = 16; o > 0; o >>= 1)
            es += __shfl_xor_sync(0xffffffffu, es, o);
        if (lane == 0) {
            out[t * BB + b] = (float)a;
            logp += unorderf(wmax) - __logf(es);
        }
    }
    if (lane == 0) out[NN * BB + b] = logp;
}

// ---------------------------------------------------------------------------
extern "C" void kernel_launch(void* const* d_in, const int* in_sizes, int n_in,
                              void* d_out, int out_size) {
    const float* hvec = (const float*)d_in[0];
    const float* hbar = (const float*)d_in[1];
    const float* qvp  = (const float*)d_in[2];
    const float* kvp  = (const float*)d_in[3];
    const float* vec1 = (const float*)d_in[4];
    const float* vecf = (const float*)d_in[5];
    float* out = (float*)d_out;

    const int smG = 4 * CH * GSTR * 4;   // 67584 B
    cudaFuncSetAttribute(kGemm, cudaFuncAttributeMaxDynamicSharedMemorySize, smG);

    float *pA, *pHT, *pMT, *pG;
    cudaGetSymbolAddress((void**)&pA,  g_A);
    cudaGetSymbolAddress((void**)&pHT, g_hT);
    cudaGetSymbolAddress((void**)&pMT, g_MT);
    cudaGetSymbolAddress((void**)&pG,  g_G);

    kA<<<DD, DD>>>(qvp, kvp);
    kT<<<dim3(NN / 32, DD / 32, BB), dim3(32, 8)>>>(hvec);
    kVec<<<BB, DD>>>(hbar, vec1, vecf);
    kSB<<<BB, NN>>>();
    kGemm<<<dim3(NN / 128, 1, BB), 256, smG>>>(
        pMT, pA, pHT, 0, (size_t)DD * NN, (size_t)DD * NN, DD, NN, NN);
    kGemm<<<dim3(NN / 128, NN / 128, BB), 256, smG>>>(
        pG, pMT, pHT, (size_t)DD * NN, (size_t)DD * NN, (size_t)NN * NN, NN, NN, NN);
    kD<<<BB, 32>>>(out);
}

// round 14
// speedup vs baseline: 1.4379x; 1.2217x over previous
#include <cuda_runtime.h>
#include <math.h>

#define BB 256
#define NN 384
#define DD 128
#define NEGV -1e9f
#define GSTR 132
#define CH 32

// ---------------- device scratch (static, no allocation) ----------------
__device__ float    g_A[DD * DD];
__device__ float    g_hT[BB * DD * NN];
__device__ float    g_MT[BB * DD * NN];
__device__ unsigned g_SORD[(size_t)BB * NN * NN];   // orderf(score) table
__device__ float    g_hbarA[BB * DD];
__device__ float    g_vA[DD];
__device__ float    g_sHB[BB * NN];
__device__ float    g_sV[BB * NN];
__device__ float    g_SBF[BB * NN];
__device__ int      g_a0[BB];

// ---------------- packed fp32x2 helpers ----------------
__device__ __forceinline__ void ffma2(unsigned long long& d,
                                      unsigned long long a,
                                      unsigned long long b) {
    asm("fma.rn.f32x2 %0, %1, %2, %0;" : "+l"(d) : "l"(a), "l"(b));
}
__device__ __forceinline__ unsigned long long pack2(float lo, float hi) {
    unsigned long long r;
    asm("mov.b64 %0, {%1, %2};" : "=l"(r) : "f"(lo), "f"(hi));
    return r;
}
__device__ __forceinline__ float2 unpack2(unsigned long long v) {
    float2 f;
    asm("mov.b64 {%0, %1}, %2;" : "=f"(f.x), "=f"(f.y) : "l"(v));
    return f;
}

// order-preserving float<->u32 bijection (total order == fp32 compare)
__device__ __forceinline__ unsigned orderf(float f) {
    unsigned b = __float_as_uint(f);
    return (b & 0x80000000u) ? ~b : (b | 0x80000000u);
}
__device__ __forceinline__ float unorderf(unsigned o) {
    unsigned b = (o & 0x80000000u) ? (o & 0x7fffffffu) : ~o;
    return __uint_as_float(b);
}

// ---------------------------------------------------------------------------
// Bit-faithful port of XLA's EmitFastTanh (with_fma=true). DO NOT TOUCH.
// ---------------------------------------------------------------------------
__device__ __forceinline__ float xla_tanh(float x) {
    const float kClamp = 7.99881172180175781f;
    float xc = fminf(fmaxf(x, -kClamp), kClamp);
    float x2 = xc * xc;
    float p = fmaf(x2, -2.76076847742355e-16f, 2.00018790482477e-13f);
    p = fmaf(x2, p, -8.60467152213735e-11f);
    p = fmaf(x2, p,  5.12229709037114e-08f);
    p = fmaf(x2, p,  1.48572235717979e-05f);
    p = fmaf(x2, p,  6.37261928875436e-04f);
    p = fmaf(x2, p,  4.89352455891786e-03f);
    p = xc * p;
    float q = fmaf(x2, 1.19825839466702e-06f, 1.18534705686654e-04f);
    q = fmaf(x2, q, 2.26843463243900e-03f);
    q = fmaf(x2, q, 4.89352518554385e-03f);
    float r = p / q;
    return (fabsf(x) < 0.0004f) ? x : r;
}

// ---------------------------------------------------------------------------
__global__ void kA(const float* __restrict__ qv, const float* __restrict__ kv) {
    __shared__ float wk[DD];
    int m = blockIdx.x, k = threadIdx.x;
    wk[k] = kv[m * DD + k];
    __syncthreads();
    float s = 0.f;
    #pragma unroll 8
    for (int j = 0; j < DD; j++) s = fmaf(qv[k * DD + j], wk[j], s);
    g_A[k * DD + m] = s;
}

__global__ void kT(const float* __restrict__ hvec) {
    __shared__ float tile[32][33];
    int b = blockIdx.z;
    int n0 = blockIdx.x * 32, d0 = blockIdx.y * 32;
    int tx = threadIdx.x, ty = threadIdx.y;
    #pragma unroll
    for (int i = 0; i < 32; i += 8)
        tile[ty + i][tx] = hvec[((size_t)b * NN + n0 + ty + i) * DD + d0 + tx];
    __syncthreads();
    #pragma unroll
    for (int i = 0; i < 32; i += 8)
        g_hT[((size_t)b * DD + d0 + ty + i) * NN + n0 + tx] = tile[tx][ty + i];
}

__global__ void kVec(const float* __restrict__ hbar,
                     const float* __restrict__ vec1,
                     const float* __restrict__ vecf) {
    __shared__ float hb[DD], vv[DD];
    int b = blockIdx.x, m = threadIdx.x;
    hb[m] = hbar[b * DD + m];
    if (b == 0) vv[m] = vec1[m] + vecf[m];
    __syncthreads();
    float acc = 0.f;
    #pragma unroll 8
    for (int k = 0; k < DD; k++) acc = fmaf(hb[k], g_A[k * DD + m], acc);
    g_hbarA[b * DD + m] = acc;
    if (b == 0) {
        float a2 = 0.f;
        #pragma unroll 8
        for (int k = 0; k < DD; k++) a2 = fmaf(vv[k], g_A[k * DD + m], a2);
        g_vA[m] = a2;
    }
}

// ---------------------------------------------------------------------------
// K_SB: sHB/sV per node + a0 = argmax of t=0 scores (lowest-index ties).
// ---------------------------------------------------------------------------
__global__ void __launch_bounds__(NN) kSB() {
    __shared__ float sb[DD], sv[DD];
    __shared__ unsigned rov[12];
    __shared__ int rix[12];
    int b = blockIdx.x, n = threadIdx.x;
    int lane = n & 31, wid = n >> 5;
    if (n < DD) { sb[n] = g_hbarA[b * DD + n]; sv[n] = g_vA[n]; }
    __syncthreads();
    const float* hTb = g_hT + (size_t)b * DD * NN;
    float a0 = 0.f, a1 = 0.f, a2 = 0.f, a3 = 0.f;
    float c0 = 0.f, c1 = 0.f, c2 = 0.f, c3 = 0.f;
    #pragma unroll 8
    for (int d = 0; d < DD; d += 4) {
        float h0 = hTb[(size_t)(d + 0) * NN + n];
        float h1 = hTb[(size_t)(d + 1) * NN + n];
        float h2 = hTb[(size_t)(d + 2) * NN + n];
        float h3 = hTb[(size_t)(d + 3) * NN + n];
        a0 = fmaf(h0, sb[d + 0], a0); c0 = fmaf(h0, sv[d + 0], c0);
        a1 = fmaf(h1, sb[d + 1], a1); c1 = fmaf(h1, sv[d + 1], c1);
        a2 = fmaf(h2, sb[d + 2], a2); c2 = fmaf(h2, sv[d + 2], c2);
        a3 = fmaf(h3, sb[d + 3], a3); c3 = fmaf(h3, sv[d + 3], c3);
    }
    float sHB = (a0 + a1) + (a2 + a3);
    float sV  = (c0 + c1) + (c2 + c3);
    g_sHB[b * NN + n] = sHB;
    g_sV[b * NN + n]  = sV;

    // t=0 argmax (exact same float math as kD's t=0)
    float score0 = 10.f * xla_tanh((sHB + sV) * 0.25f);
    unsigned ov = orderf(score0);
    unsigned wmax = __reduce_max_sync(0xffffffffu, ov);
    unsigned bal  = __ballot_sync(0xffffffffu, ov == wmax);
    if (lane == 0) { rov[wid] = wmax; rix[wid] = (wid << 5) + (__ffs(bal) - 1); }
    __syncthreads();
    if (n == 0) {
        unsigned bv = rov[0]; int bi = rix[0];
        #pragma unroll
        for (int w = 1; w < 12; w++)
            if (rov[w] > bv) { bv = rov[w]; bi = rix[w]; }  // strict > keeps lowest
        g_a0[b] = bi;
    }
}

// ---------------------------------------------------------------------------
// K_Row: SBF[b][n] = sHB[b][n] + G[a0][n], G[a0][n] via the SAME d-ascending
// fma chain as the gemm lane (bit-identical).
// ---------------------------------------------------------------------------
__global__ void __launch_bounds__(NN) kRow() {
    __shared__ float mtc[DD];
    int b = blockIdx.x, n = threadIdx.x;
    int a0 = g_a0[b];
    if (n < DD) mtc[n] = g_MT[((size_t)b * DD + n) * NN + a0];
    __syncthreads();
    const float* hTb = g_hT + (size_t)b * DD * NN;
    float acc = 0.f;
    #pragma unroll 8
    for (int d = 0; d < DD; d++)
        acc = fmaf(mtc[d], hTb[(size_t)d * NN + n], acc);
    g_SBF[b * NN + n] = g_sHB[b * NN + n] + acc;
}

// ---------------------------------------------------------------------------
// K_Gemm (MT): unchanged cp.async double-buffered 128x128 tile.
// ---------------------------------------------------------------------------
extern __shared__ float dynsm[];
__device__ __forceinline__ void cpa16(unsigned s, const void* g) {
    asm volatile("cp.async.ca.shared.global [%0], [%1], 16;" :: "r"(s), "l"(g));
}

template <bool EPI>
__global__ void __launch_bounds__(256, 2)
kGemmT(float* __restrict__ Cg, const float* __restrict__ Ag,
       const float* __restrict__ Bg, unsigned* __restrict__ Og,
       size_t sAb, size_t sBb, size_t sCb, int ldA, int ldB, int ldC) {
    int b = blockIdx.z;
    int r0 = blockIdx.y * 128, c0 = blockIdx.x * 128;
    int tid = threadIdx.x;
    int ty = tid >> 4, tx = tid & 15;

    const float* Ab = Ag + (size_t)b * sAb;
    const float* Bb = Bg + (size_t)b * sBb;
    unsigned sbase = (unsigned)__cvta_generic_to_shared(dynsm);

    unsigned long long acc2[32];
    #pragma unroll
    for (int j = 0; j < 32; j++) acc2[j] = 0ull;

    auto issue = [&](int c, int st) {
        unsigned Ms = sbase + (unsigned)(st * 2 * CH * GSTR) * 4u;
        unsigned Hs = Ms + (unsigned)(CH * GSTR) * 4u;
        const float* Asrc = Ab + (size_t)(c * CH) * ldA + r0;
        const float* Bsrc = Bb + (size_t)(c * CH) * ldB + c0;
        #pragma unroll
        for (int i = tid; i < CH * 32; i += 256) {
            int d = i >> 5, v = i & 31;
            cpa16(Ms + (unsigned)(d * GSTR + v * 4) * 4u, Asrc + (size_t)d * ldA + v * 4);
            cpa16(Hs + (unsigned)(d * GSTR + v * 4) * 4u, Bsrc + (size_t)d * ldB + v * 4);
        }
        asm volatile("cp.async.commit_group;");
    };

    issue(0, 0);
    #pragma unroll
    for (int c = 0; c < 4; c++) {
        if (c < 3) {
            issue(c + 1, (c + 1) & 1);
            asm volatile("cp.async.wait_group 1;");
        } else {
            asm volatile("cp.async.wait_group 0;");
        }
        __syncthreads();
        float* Ms = dynsm + (c & 1) * 2 * CH * GSTR;
        float* Hs = Ms + CH * GSTR;
        #pragma unroll 4
        for (int d = 0; d < CH; d++) {
            const float4* ar = (const float4*)(Ms + d * GSTR + ty * 8);
            float4 A0 = ar[0], A1 = ar[1];
            ulonglong2 B0 = *(const ulonglong2*)(Hs + d * GSTR + tx * 4);
            ulonglong2 B1 = *(const ulonglong2*)(Hs + d * GSTR + 64 + tx * 4);
            unsigned long long bl[4] = {B0.x, B0.y, B1.x, B1.y};
            float af[8] = {A0.x, A0.y, A0.z, A0.w, A1.x, A1.y, A1.z, A1.w};
            #pragma unroll
            for (int r = 0; r < 8; r++) {
                unsigned long long ad = pack2(af[r], af[r]);
                #pragma unroll
                for (int cc = 0; cc < 4; cc++) ffma2(acc2[r * 4 + cc], bl[cc], ad);
            }
        }
        __syncthreads();
    }

    if (!EPI) {
        #pragma unroll
        for (int r = 0; r < 8; r++) {
            float* crow = Cg + (size_t)b * sCb + (size_t)(r0 + ty * 8 + r) * ldC + c0;
            ulonglong2 w0; w0.x = acc2[r * 4 + 0]; w0.y = acc2[r * 4 + 1];
            ulonglong2 w1; w1.x = acc2[r * 4 + 2]; w1.y = acc2[r * 4 + 3];
            *(ulonglong2*)(crow + tx * 4) = w0;
            *(ulonglong2*)(crow + 64 + tx * 4) = w1;
        }
    } else {
        // fused epilogue: SORD = orderf(10 * tanh(0.25 * (SBF[n] + G[l][n])))
        const float* sbfp = g_SBF + b * NN + c0;
        float4 sb0 = *(const float4*)(sbfp + tx * 4);
        float4 sb1 = *(const float4*)(sbfp + 64 + tx * 4);
        float sbf[8] = {sb0.x, sb0.y, sb0.z, sb0.w, sb1.x, sb1.y, sb1.z, sb1.w};
        #pragma unroll
        for (int r = 0; r < 8; r++) {
            float gvals[8];
            #pragma unroll
            for (int cc = 0; cc < 4; cc++) {
                float2 f = unpack2(acc2[r * 4 + cc]);
                gvals[2 * cc] = f.x; gvals[2 * cc + 1] = f.y;
            }
            unsigned ords[8];
            #pragma unroll
            for (int e = 0; e < 8; e++) {
                float s = sbf[e] + gvals[e];
                ords[e] = orderf(10.f * xla_tanh(s * 0.25f));
            }
            unsigned* orow = Og + ((size_t)b * NN + r0 + ty * 8 + r) * NN + c0;
            *(uint4*)(orow + tx * 4)      = make_uint4(ords[0], ords[1], ords[2], ords[3]);
            *(uint4*)(orow + 64 + tx * 4) = make_uint4(ords[4], ords[5], ords[6], ords[7]);
        }
    }
}

// ---------------------------------------------------------------------------
// K_D: one warp per batch. Lane owns nodes n = lane*12 + r. For t>=1 the
// scores are PRE-TANHED u32 keys (SORD rows) -> loop chain = load + compares
// + 2 redux. exp/logp reconstructed via unorderf (bijective) off the chain,
// summed in the same r-ascending order as before.
// ---------------------------------------------------------------------------
__global__ void __launch_bounds__(32) kD(float* __restrict__ out) {
    const int b = blockIdx.x, lane = threadIdx.x;
    const int nb = lane * 12;

    float sHB[12], sV[12];
    {
        const float4* p1 = (const float4*)(g_sHB + b * NN + nb);
        const float4* p2 = (const float4*)(g_sV  + b * NN + nb);
        #pragma unroll
        for (int q = 0; q < 3; q++) {
            float4 v1 = __ldg(p1 + q), v2 = __ldg(p2 + q);
            sHB[4*q+0] = v1.x; sHB[4*q+1] = v1.y; sHB[4*q+2] = v1.z; sHB[4*q+3] = v1.w;
            sV [4*q+0] = v2.x; sV [4*q+1] = v2.y; sV [4*q+2] = v2.z; sV [4*q+3] = v2.w;
        }
    }

    const unsigned* Ob = g_SORD + (size_t)b * NN * NN;
    unsigned vismask = 0;
    float logp = 0.f;
    int a;
    unsigned ords[12];

    // ---- t = 0 (scores from sHB+sV, same math as R13) ----
    {
        float best = -3.0e38f; int nbest = 0x7fffffff; float es = 0.f;
        float sc[12];
        #pragma unroll
        for (int r = 0; r < 12; r++) {
            sc[r] = 10.f * xla_tanh((sHB[r] + sV[r]) * 0.25f);
            es += __expf(sc[r]);
            if (sc[r] > best) { best = sc[r]; nbest = nb + r; }
        }
        unsigned ov   = orderf(best);
        unsigned wmax = __reduce_max_sync(0xffffffffu, ov);
        unsigned cand = (ov == wmax) ? (unsigned)nbest : 0xffffffffu;
        a = (int)__reduce_min_sync(0xffffffffu, cand);
        if (a >= nb && a < nb + 12) vismask |= 1u << (a - nb);

        // first SORD row load
        const uint4* op = (const uint4*)(Ob + (size_t)a * NN + nb);
        #pragma unroll
        for (int q = 0; q < 3; q++) {
            uint4 o4 = __ldg(op + q);
            ords[4*q+0] = o4.x; ords[4*q+1] = o4.y; ords[4*q+2] = o4.z; ords[4*q+3] = o4.w;
        }

        #pragma unroll
        for (int o = 16; o > 0; o >>= 1)
            es += __shfl_xor_sync(0xffffffffu, es, o);
        if (lane == 0) {
            out[0 * BB + b] = (float)a;
            logp += unorderf(wmax) - __logf(es);
        }
    }

    // ---- t = 1 .. 383 ----
    for (int t = 1; t < NN; t++) {
        unsigned vm_old = vismask;

        // masked local argmax over precomputed keys (ascending r, strict >)
        unsigned best = 0; int nbest = 0x7fffffff;
        #pragma unroll
        for (int r = 0; r < 12; r++) {
            unsigned mo = ((vm_old >> r) & 1u) ? 0u : ords[r];
            if (mo > best) { best = mo; nbest = nb + r; }
        }
        unsigned wmax = __reduce_max_sync(0xffffffffu, best);
        unsigned cand = (best == wmax) ? (unsigned)nbest : 0xffffffffu;
        a = (int)__reduce_min_sync(0xffffffffu, cand);
        if (a >= nb && a < nb + 12) vismask |= 1u << (a - nb);

        // CRITICAL: issue next row loads immediately
        unsigned nxt[12];
        {
            const uint4* op = (const uint4*)(Ob + (size_t)a * NN + nb);
            #pragma unroll
            for (int q = 0; q < 3; q++) {
                uint4 o4 = __ldg(op + q);
                nxt[4*q+0] = o4.x; nxt[4*q+1] = o4.y; nxt[4*q+2] = o4.z; nxt[4*q+3] = o4.w;
            }
        }

        // logp bookkeeping (off the chain): exp of exact scores
        float es = 0.f;
        #pragma unroll
        for (int r = 0; r < 12; r++)
            es += ((vm_old >> r) & 1u) ? 0.f : __expf(unorderf(ords[r]));
        #pragma unroll
        for (int o = 16; o > 0; o >>= 1)
            es += __shfl_xor_sync(0xffffffffu, es, o);
        if (lane == 0) {
            out[t * BB + b] = (float)a;
            logp += unorderf(wmax) - __logf(es);
        }

        #pragma unroll
        for (int r = 0; r < 12; r++) ords[r] = nxt[r];
    }
    if (lane == 0) out[NN * BB + b] = logp;
}

// ---------------------------------------------------------------------------
extern "C" void kernel_launch(void* const* d_in, const int* in_sizes, int n_in,
                              void* d_out, int out_size) {
    const float* hvec = (const float*)d_in[0];
    const float* hbar = (const float*)d_in[1];
    const float* qvp  = (const float*)d_in[2];
    const float* kvp  = (const float*)d_in[3];
    const float* vec1 = (const float*)d_in[4];
    const float* vecf = (const float*)d_in[5];
    float* out = (float*)d_out;

    const int smG = 4 * CH * GSTR * 4;   // 67584 B
    cudaFuncSetAttribute(kGemmT<false>, cudaFuncAttributeMaxDynamicSharedMemorySize, smG);
    cudaFuncSetAttribute(kGemmT<true>,  cudaFuncAttributeMaxDynamicSharedMemorySize, smG);

    float *pA, *pHT, *pMT;
    unsigned* pO;
    cudaGetSymbolAddress((void**)&pA,  g_A);
    cudaGetSymbolAddress((void**)&pHT, g_hT);
    cudaGetSymbolAddress((void**)&pMT, g_MT);
    cudaGetSymbolAddress((void**)&pO,  g_SORD);

    kA<<<DD, DD>>>(qvp, kvp);
    kT<<<dim3(NN / 32, DD / 32, BB), dim3(32, 8)>>>(hvec);
    kVec<<<BB, DD>>>(hbar, vec1, vecf);
    kSB<<<BB, NN>>>();
    kGemmT<false><<<dim3(NN / 128, 1, BB), 256, smG>>>(
        pMT, pA, pHT, nullptr, 0, (size_t)DD * NN, (size_t)DD * NN, DD, NN, NN);
    kRow<<<BB, NN>>>();
    kGemmT<true><<<dim3(NN / 128, NN / 128, BB), 256, smG>>>(
        nullptr, pMT, pHT, pO, (size_t)DD * NN, (size_t)DD * NN, 0, NN, NN, NN);
    kD<<<BB, 32>>>(out);
}